// round 1
// baseline (speedup 1.0000x reference)
#include <cuda_runtime.h>
#include <math.h>

#define NN 128
#define PITCH 129
#define BATCH 512
#define NPAIRS 8128
#define NTHREADS 512
#define TSTEPS 10

struct __align__(16) Smem {
  float2 DW[NN * PITCH];   // (d, w) pairs, pitch-129 to kill bank conflicts
  float  BG[NN * PITCH];   // Gram matrix (deflated in place)
  float4 Xs[NN];           // coordinates (x,y,z,0)
  float4 part[3 * NN];     // cross-warp partial sums
  unsigned bits[NN * 4];   // adjacency bitmask, row-major 4 words/row
  float  rs[NN];           // row sums of D^2
  float  u[NN];            // power-iteration vector
  float  scal[8];          // 0:invN 1:M*invN^2 2:0.4/S 4:bcast scalar
  int    icnt[4];          // 0: sum(adj)
};

__device__ __forceinline__ float softplus_f(float x) {
  // matches jax.nn.softplus = max(x,0) + log1p(exp(-|x|))
  return fmaxf(x, 0.0f) + log1pf(__expf(-fabsf(x)));
}

__global__ void __launch_bounds__(NTHREADS, 1)
ts_gcn_kernel(const float* __restrict__ edge_pred,
              const int*   __restrict__ adj,
              const float* __restrict__ d_init,
              const float* __restrict__ u_init,
              const float* __restrict__ x_noise,
              float*       __restrict__ out)
{
  extern __shared__ __align__(16) char smem_raw[];
  Smem* sm = reinterpret_cast<Smem*>(smem_raw);
  const int b   = blockIdx.x;
  const int tid = threadIdx.x;
  const int i_d = tid & (NN - 1);   // row owned in row-parallel phases
  const int h_d = tid >> 7;         // which quarter of j-range (0..3)
  const float d0 = __ldg(d_init);

  const float2* epb  = reinterpret_cast<const float2*>(edge_pred) + (size_t)b * NN * NN;
  const int*    adjb = adj + (size_t)b * NN * NN;

  // ---------------- Phase A1: stage raw edge_pred into SMEM (coalesced) ----
  if (tid == 0) sm->icnt[0] = 0;
  sm->bits[tid] = 0u;
  for (int idx = tid; idx < NN * NN; idx += NTHREADS)
    sm->DW[(idx >> 7) * PITCH + (idx & (NN - 1))] = epb[idx];
  __syncthreads();

  // ---------------- Phase A2: symmetrize + softplus + adj mask (upper tri) -
  // Each (i<j) pair is owned by exactly one thread: reads raw [i][j],[j][i],
  // writes (d,w) to both. No races.
  for (int p = tid; p < NPAIRS; p += NTHREADS) {
    int i = (int)(0.5f * (255.0f - sqrtf(65025.0f - 8.0f * (float)p)));
    while ((((i + 1) * (255 - (i + 1))) >> 1) <= p) ++i;
    while (((i * (255 - i)) >> 1) > p) --i;
    int j = i + 1 + (p - ((i * (255 - i)) >> 1));
    float2 e1 = sm->DW[i * PITCH + j];
    float2 e2 = sm->DW[j * PITCH + i];
    int a = adjb[i * NN + j];
    float2 dw = make_float2(0.0f, 0.0f);
    if (a) {
      dw.x = softplus_f(d0 + e1.x + e2.x);
      dw.y = softplus_f(d0 + e1.y + e2.y);
      atomicOr(&sm->bits[(i << 2) + (j >> 5)], 1u << (j & 31));
      atomicOr(&sm->bits[(j << 2) + (i >> 5)], 1u << (i & 31));
    }
    sm->DW[i * PITCH + j] = dw;
    sm->DW[j * PITCH + i] = dw;
  }
  if (tid < NN) sm->DW[tid * PITCH + tid] = make_float2(0.0f, 0.0f);
  __syncthreads();

  // ---------------- Phase B: S = sum(mask), row sums of D^2 ---------------
  {
    int c = __popc(sm->bits[tid]);
    #pragma unroll
    for (int o = 16; o; o >>= 1) c += __shfl_xor_sync(0xffffffffu, c, o);
    if ((tid & 31) == 0) atomicAdd(&sm->icnt[0], c);
  }
  float rpart = 0.0f;
  {
    const float2* row = sm->DW + i_d * PITCH + h_d * 32;
    #pragma unroll 8
    for (int jj = 0; jj < 32; ++jj) { float d = row[jj].x; rpart = fmaf(d, d, rpart); }
    if (h_d) sm->part[(h_d - 1) * NN + i_d].x = rpart;
  }
  __syncthreads();
  if (h_d == 0) {
    rpart += sm->part[i_d].x + sm->part[NN + i_d].x + sm->part[2 * NN + i_d].x;
    sm->rs[i_d] = rpart;
  }
  __syncthreads();
  if (tid < 32) {
    float m = sm->rs[tid] + sm->rs[tid + 32] + sm->rs[tid + 64] + sm->rs[tid + 96];
    #pragma unroll
    for (int o = 16; o; o >>= 1) m += __shfl_xor_sync(0xffffffffu, m, o);
    if (tid == 0) {
      float Nmol = 1.0f + (float)(__popc(sm->bits[0]) + __popc(sm->bits[1]) +
                                  __popc(sm->bits[2]) + __popc(sm->bits[3]));
      float invN = 1.0f / Nmol;
      sm->scal[0] = invN;
      sm->scal[1] = m * invN * invN;        // D_mean term
      float S = 128.0f + (float)sm->icnt[0]; // sum(mask): diag ones + adj
      sm->scal[2] = 0.4f / S;                // = 4*STEP_EPS / S
    }
  }
  __syncthreads();

  // ---------------- Phase B2: build Gram matrix BG -------------------------
  {
    float invN = sm->scal[0], Moff = sm->scal[1];
    unsigned wb = sm->bits[(i_d << 2) + h_d];
    float rsi = sm->rs[i_d];
    int j0 = h_d * 32;
    #pragma unroll 8
    for (int jj = 0; jj < 32; ++jj) {
      int j = j0 + jj;
      float d = sm->DW[i_d * PITCH + j].x;
      bool m = (((wb >> jj) & 1u) != 0u) || (j == i_d);
      float v = -0.5f * (fmaf(d, d, Moff) - (rsi + sm->rs[j]) * invN);
      sm->BG[i_d * PITCH + j] = m ? v : 0.0f;
    }
  }
  if (tid < NN) {
    sm->u[tid] = u_init[((size_t)b * NN + tid) * 3];
    sm->Xs[tid].w = 0.0f;
  }
  __syncthreads();

  // ---------------- Phase C: rank-3 power iteration with deflation ---------
  for (int k = 0; k < 3; ++k) {
    if (k) {
      if (tid < NN) sm->u[tid] = u_init[((size_t)b * NN + tid) * 3 + k];
      __syncthreads();
    }
    for (int it = 0; it < 10; ++it) {
      if (tid < 32) {
        float s = 0.0f;
        #pragma unroll
        for (int r = 0; r < 4; ++r) { float v = sm->u[tid + r * 32]; s = fmaf(v, v, s); }
        #pragma unroll
        for (int o = 16; o; o >>= 1) s += __shfl_xor_sync(0xffffffffu, s, o);
        if (tid == 0) sm->scal[4] = 1.0f / fmaxf(sqrtf(s), 0.001f);
      }
      __syncthreads();
      float acc = 0.0f;
      {
        const float* bgrow = sm->BG + i_d * PITCH + h_d * 32;
        const float* useg  = sm->u + h_d * 32;
        #pragma unroll 8
        for (int jj = 0; jj < 32; ++jj) acc = fmaf(bgrow[jj], useg[jj], acc);
      }
      if (h_d) sm->part[(h_d - 1) * NN + i_d].x = acc;
      __syncthreads();
      if (h_d == 0) {
        acc += sm->part[i_d].x + sm->part[NN + i_d].x + sm->part[2 * NN + i_d].x;
        sm->u[i_d] = acc * sm->scal[4];   // A @ (u/|u|)
      }
      __syncthreads();
    }
    if (tid < 32) {
      float s = 0.0f;
      #pragma unroll
      for (int r = 0; r < 4; ++r) { float v = sm->u[tid + r * 32]; s = fmaf(v, v, s); }
      #pragma unroll
      for (int o = 16; o; o >>= 1) s += __shfl_xor_sync(0xffffffffu, s, o);
      if (tid == 0) sm->scal[4] = rsqrtf(sqrtf(s + 0.01f)); // (eig+0.01)^-0.25
    }
    __syncthreads();
    if (tid < NN) {
      float uk = sm->u[tid] * sm->scal[4];
      sm->u[tid] = uk;
      reinterpret_cast<float*>(&sm->Xs[tid])[k] =
          uk + x_noise[((size_t)b * NN + tid) * 3 + k];
    }
    __syncthreads();
    if (k < 2) {  // deflate: BG -= u u^T
      float ui = sm->u[i_d];
      float* bgrow = sm->BG + i_d * PITCH + h_d * 32;
      const float* useg = sm->u + h_d * 32;
      #pragma unroll 8
      for (int jj = 0; jj < 32; ++jj) bgrow[jj] = fmaf(-ui, useg[jj], bgrow[jj]);
      __syncthreads();
    }
  }

  // ---------------- Phase D: 10 gradient-descent steps ---------------------
  const float c = sm->scal[2];   // 0.4/S
  for (int ts = 0; ts < TSTEPS; ++ts) {
    float alpha = 0.1f + 4.9f * ((float)(TSTEPS - ts) * 0.1f);
    float4 xi = sm->Xs[i_d];
    float ax = 0.0f, ay = 0.0f, az = 0.0f;
    {
      const float2* dwrow = sm->DW + i_d * PITCH + h_d * 32;
      const float4* xrow  = sm->Xs + h_d * 32;
      #pragma unroll 8
      for (int jj = 0; jj < 32; ++jj) {
        float4 xj = xrow[jj];                 // broadcast across warp
        float dx = xi.x - xj.x;
        float dy = xi.y - xj.y;
        float dz = xi.z - xj.z;
        float s  = fmaf(dx, dx, fmaf(dy, dy, fmaf(dz, dz, 0.01f)));
        float2 dw = dwrow[jj];
        float rinv = rsqrtf(s);
        float coef = dw.y * fmaf(dw.x, rinv, -1.0f); // w*(d/Dx - 1)
        ax = fmaf(coef, dx, ax);
        ay = fmaf(coef, dy, ay);
        az = fmaf(coef, dz, az);
      }
    }
    if (h_d) sm->part[(h_d - 1) * NN + i_d] = make_float4(ax, ay, az, 0.0f);
    __syncthreads();
    if (h_d == 0) {
      float4 p1 = sm->part[i_d], p2 = sm->part[NN + i_d], p3 = sm->part[2 * NN + i_d];
      float gx = (ax + p1.x + p2.x + p3.x) * c;   // dx = -eps*grad
      float gy = (ay + p1.y + p2.y + p3.y) * c;
      float gz = (az + p1.z + p2.z + p3.z) * c;
      float sp = sqrtf(fmaf(gx, gx, fmaf(gy, gy, fmaf(gz, gz, 0.001f))));
      float sc = alpha * tanhf(sp / alpha) / sp;
      xi.x = fmaf(gx, sc, xi.x);
      xi.y = fmaf(gy, sc, xi.y);
      xi.z = fmaf(gz, sc, xi.z);
      sm->Xs[i_d] = xi;
    }
    __syncthreads();
  }

  // ---------------- Phase E: output = adj * distances(X) -------------------
  float* outb = out + (size_t)b * NN * NN;
  for (int g = tid; g < (NN * NN) / 4; g += NTHREADS) {
    int i  = g >> 5;
    int j0 = (g & 31) * 4;
    float4 xi = sm->Xs[i];
    unsigned wb = sm->bits[(i << 2) + (j0 >> 5)];
    float4 r;
    #pragma unroll
    for (int m = 0; m < 4; ++m) {
      int j = j0 + m;
      float4 xj = sm->Xs[j];
      float dx = xi.x - xj.x, dy = xi.y - xj.y, dz = xi.z - xj.z;
      float s = fmaf(dx, dx, fmaf(dy, dy, fmaf(dz, dz, 0.01f)));
      float v = ((wb >> (j & 31)) & 1u) ? sqrtf(s) : 0.0f;
      reinterpret_cast<float*>(&r)[m] = v;
    }
    reinterpret_cast<float4*>(outb)[g] = r;
  }
}

extern "C" void kernel_launch(void* const* d_in, const int* in_sizes, int n_in,
                              void* d_out, int out_size) {
  const float* edge_pred = (const float*)d_in[0];
  const int*   adj       = (const int*)  d_in[1];
  const float* d_init    = (const float*)d_in[2];
  const float* u_init    = (const float*)d_in[3];
  const float* x_noise   = (const float*)d_in[4];
  float* out = (float*)d_out;

  size_t smem = sizeof(Smem);
  cudaFuncSetAttribute(ts_gcn_kernel,
                       cudaFuncAttributeMaxDynamicSharedMemorySize, (int)smem);
  ts_gcn_kernel<<<BATCH, NTHREADS, smem>>>(edge_pred, adj, d_init, u_init,
                                           x_noise, out);
}